// round 2
// baseline (speedup 1.0000x reference)
#include <cuda_runtime.h>
#include <math.h>

#define DIMC 512
#define NH 8
#define HD 64
#define NSEQ 4096
#define BATCH 2
#define MROWS (BATCH*NSEQ)   /* 8192 */

// -------- scratch (static device allocations; no cudaMalloc allowed) --------
__device__ float g_Q [MROWS*DIMC];
__device__ float g_K [MROWS*DIMC];
__device__ float g_V [MROWS*DIMC];
__device__ float g_A [MROWS*DIMC];
__device__ float g_CI[MROWS*DIMC];
__device__ float g_CO[MROWS*DIMC];

// ---------------------------------------------------------------------------
// GEMM NT: C[M,512] = A[M,512] @ W[512,512]^T   (torch Linear)
// tile 128x128, ktile 16, 256 threads, 8x8 microtile (stride-16 pattern)
// ---------------------------------------------------------------------------
template<bool ADD>
__global__ __launch_bounds__(256)
void gemm_nt(const float* __restrict__ A, const float* __restrict__ W,
             float* __restrict__ C)
{
    __shared__ float As[16][129];
    __shared__ float Ws[16][129];
    const int tid = threadIdx.x;
    const int tx = tid & 15, ty = tid >> 4;
    const int m0 = blockIdx.x * 128;
    const int n0 = blockIdx.y * 128;

    float acc[8][8];
#pragma unroll
    for (int i = 0; i < 8; i++)
#pragma unroll
        for (int j = 0; j < 8; j++) acc[i][j] = 0.f;

    const int r  = tid >> 2;        // 0..63
    const int kq = (tid & 3) * 4;   // 0,4,8,12

    for (int k0 = 0; k0 < DIMC; k0 += 16) {
#pragma unroll
        for (int p = 0; p < 2; p++) {
            int row = r + p * 64;
            float4 va = *(const float4*)&A[(size_t)(m0 + row) * DIMC + k0 + kq];
            As[kq+0][row] = va.x; As[kq+1][row] = va.y;
            As[kq+2][row] = va.z; As[kq+3][row] = va.w;
            float4 vw = *(const float4*)&W[(size_t)(n0 + row) * DIMC + k0 + kq];
            Ws[kq+0][row] = vw.x; Ws[kq+1][row] = vw.y;
            Ws[kq+2][row] = vw.z; Ws[kq+3][row] = vw.w;
        }
        __syncthreads();
#pragma unroll
        for (int k = 0; k < 16; k++) {
            float a[8], b[8];
#pragma unroll
            for (int i = 0; i < 8; i++) a[i] = As[k][ty + 16*i];
#pragma unroll
            for (int j = 0; j < 8; j++) b[j] = Ws[k][tx + 16*j];
#pragma unroll
            for (int i = 0; i < 8; i++)
#pragma unroll
                for (int j = 0; j < 8; j++)
                    acc[i][j] = fmaf(a[i], b[j], acc[i][j]);
        }
        __syncthreads();
    }

#pragma unroll
    for (int i = 0; i < 8; i++) {
        int m = m0 + ty + 16*i;
#pragma unroll
        for (int j = 0; j < 8; j++) {
            int n = n0 + tx + 16*j;
            if (ADD) C[(size_t)m * DIMC + n] += acc[i][j];
            else     C[(size_t)m * DIMC + n]  = acc[i][j];
        }
    }
}

// ---------------------------------------------------------------------------
// Flash attention, fp32. BM=128 queries/CTA, BN=64 keys/iter, hd=64.
// 256 threads: S micro 8x4 (rows ty+16i, cols tx+16j). Online softmax.
// smem: sQ [64][129] (d-major), sKP union (Ks [64][65] d-major / Ps [64][129]
// key-major), sV [64][64] key-major.
// ---------------------------------------------------------------------------
#define BM 128
#define BN 64
#define SQ_STR 129
#define SK_STR 65
#define SP_STR 129

__global__ __launch_bounds__(256)
void flash_attn(const float* __restrict__ Q, const float* __restrict__ K,
                const float* __restrict__ V, float* __restrict__ Aout)
{
    extern __shared__ float smem[];
    float* sQ  = smem;                 // 64*129 = 8256
    float* sKP = sQ + HD * SQ_STR;     // max(64*65, 64*129) = 8256
    float* sV  = sKP + BN * SP_STR;    // 64*64 = 4096

    const int tid = threadIdx.x;
    const int tx = tid & 15, ty = tid >> 4;
    const int m0 = blockIdx.x * BM;
    const int h  = blockIdx.y;
    const int b  = blockIdx.z;
    const float scale = 0.125f;        // hd^-0.5

    const float* Qb = Q + (size_t)b * NSEQ * DIMC + h * HD;
    const float* Kb = K + (size_t)b * NSEQ * DIMC + h * HD;
    const float* Vb = V + (size_t)b * NSEQ * DIMC + h * HD;

    // load Q tile transposed (d-major), pre-scaled
    {
        int dq = (tid & 15) * 4;
        int r0 = tid >> 4;
#pragma unroll
        for (int p = 0; p < 8; p++) {
            int rr = r0 + p * 16;
            float4 v = *(const float4*)&Qb[(size_t)(m0 + rr) * DIMC + dq];
            sQ[(dq+0)*SQ_STR + rr] = v.x * scale;
            sQ[(dq+1)*SQ_STR + rr] = v.y * scale;
            sQ[(dq+2)*SQ_STR + rr] = v.z * scale;
            sQ[(dq+3)*SQ_STR + rr] = v.w * scale;
        }
    }

    float O[8][4];
    float m_i[8], l_i[8];
#pragma unroll
    for (int i = 0; i < 8; i++) {
        m_i[i] = -1e30f; l_i[i] = 0.f;
#pragma unroll
        for (int j = 0; j < 4; j++) O[i][j] = 0.f;
    }

    for (int n0 = 0; n0 < NSEQ; n0 += BN) {
        __syncthreads();   // prev iter done with sKP/sV (also covers sQ load on iter 0)
        // load K (transposed, d-major) and V (key-major)
        {
            int dq = (tid & 15) * 4;
            int c0 = tid >> 4;
#pragma unroll
            for (int p = 0; p < 4; p++) {
                int c = c0 + p * 16;
                float4 vk = *(const float4*)&Kb[(size_t)(n0 + c) * DIMC + dq];
                sKP[(dq+0)*SK_STR + c] = vk.x;
                sKP[(dq+1)*SK_STR + c] = vk.y;
                sKP[(dq+2)*SK_STR + c] = vk.z;
                sKP[(dq+3)*SK_STR + c] = vk.w;
                float4 vv = *(const float4*)&Vb[(size_t)(n0 + c) * DIMC + dq];
                *(float4*)&sV[c * HD + dq] = vv;
            }
        }
        __syncthreads();

        // S = (Q*scale) @ K^T  micro 8x4
        float S[8][4];
#pragma unroll
        for (int i = 0; i < 8; i++)
#pragma unroll
            for (int j = 0; j < 4; j++) S[i][j] = 0.f;
#pragma unroll 8
        for (int k = 0; k < HD; k++) {
            float a[8], bq[4];
#pragma unroll
            for (int i = 0; i < 8; i++) a[i]  = sQ [k*SQ_STR + ty + 16*i];
#pragma unroll
            for (int j = 0; j < 4; j++) bq[j] = sKP[k*SK_STR + tx + 16*j];
#pragma unroll
            for (int i = 0; i < 8; i++)
#pragma unroll
                for (int j = 0; j < 4; j++)
                    S[i][j] = fmaf(a[i], bq[j], S[i][j]);
        }

        // online softmax (row groups of 16 lanes)
#pragma unroll
        for (int i = 0; i < 8; i++) {
            float mloc = S[i][0];
#pragma unroll
            for (int j = 1; j < 4; j++) mloc = fmaxf(mloc, S[i][j]);
#pragma unroll
            for (int o = 8; o >= 1; o >>= 1)
                mloc = fmaxf(mloc, __shfl_xor_sync(0xffffffffu, mloc, o));
            float mnew  = fmaxf(m_i[i], mloc);
            float alpha = __expf(m_i[i] - mnew);
            float s = 0.f;
#pragma unroll
            for (int j = 0; j < 4; j++) {
                float p = __expf(S[i][j] - mnew);
                S[i][j] = p; s += p;
            }
#pragma unroll
            for (int o = 8; o >= 1; o >>= 1)
                s += __shfl_xor_sync(0xffffffffu, s, o);
            l_i[i] = l_i[i] * alpha + s;
            m_i[i] = mnew;
#pragma unroll
            for (int j = 0; j < 4; j++) O[i][j] *= alpha;
        }

        __syncthreads();   // everyone done reading Ks before Ps overwrites it
#pragma unroll
        for (int i = 0; i < 8; i++)
#pragma unroll
            for (int j = 0; j < 4; j++)
                sKP[(tx + 16*j)*SP_STR + (ty + 16*i)] = S[i][j];
        __syncthreads();

        // O += P @ V
#pragma unroll 8
        for (int c = 0; c < BN; c++) {
            float a[8], bv[4];
#pragma unroll
            for (int i = 0; i < 8; i++) a[i]  = sKP[c*SP_STR + ty + 16*i];
#pragma unroll
            for (int j = 0; j < 4; j++) bv[j] = sV [c*HD     + tx + 16*j];
#pragma unroll
            for (int i = 0; i < 8; i++)
#pragma unroll
                for (int j = 0; j < 4; j++)
                    O[i][j] = fmaf(a[i], bv[j], O[i][j]);
        }
    }

    // normalize + write
#pragma unroll
    for (int i = 0; i < 8; i++) {
        float inv = 1.f / l_i[i];
        int row = m0 + ty + 16*i;
#pragma unroll
        for (int j = 0; j < 4; j++) {
            int d = tx + 16*j;
            Aout[((size_t)b * NSEQ + row) * DIMC + h * HD + d] = O[i][j] * inv;
        }
    }
}

// ---------------------------------------------------------------------------
// depthwise conv over N (k=3, pad=1, cross-correlation) + bias
// ---------------------------------------------------------------------------
__global__ __launch_bounds__(256)
void dwconv(const float* __restrict__ CI, const float* __restrict__ kern,
            const float* __restrict__ bias, float* __restrict__ CO)
{
    int idx = blockIdx.x * blockDim.x + threadIdx.x;
    if (idx >= MROWS * DIMC) return;
    int c   = idx & (DIMC - 1);
    int row = idx >> 9;            // b*N + n
    int n   = row & (NSEQ - 1);
    float k0 = kern[c*3+0], k1 = kern[c*3+1], k2 = kern[c*3+2];
    float acc = bias[c] + k1 * CI[idx];
    if (n > 0)        acc += k0 * CI[idx - DIMC];
    if (n < NSEQ - 1) acc += k2 * CI[idx + DIMC];
    CO[idx] = acc;
}

// ---------------------------------------------------------------------------
extern "C" void kernel_launch(void* const* d_in, const int* in_sizes, int n_in,
                              void* d_out, int out_size)
{
    const float* x     = (const float*)d_in[0];
    const float* Wq    = (const float*)d_in[1];
    const float* Wk    = (const float*)d_in[2];
    const float* Wv    = (const float*)d_in[3];
    const float* Wattn = (const float*)d_in[4];
    const float* Wconv = (const float*)d_in[5];
    const float* dwk   = (const float*)d_in[6];
    const float* dwb   = (const float*)d_in[7];
    const float* Wcout = (const float*)d_in[8];
    float* out = (float*)d_out;

    float *Qp, *Kp, *Vp, *Ap, *CIp, *COp;
    cudaGetSymbolAddress((void**)&Qp,  g_Q);
    cudaGetSymbolAddress((void**)&Kp,  g_K);
    cudaGetSymbolAddress((void**)&Vp,  g_V);
    cudaGetSymbolAddress((void**)&Ap,  g_A);
    cudaGetSymbolAddress((void**)&CIp, g_CI);
    cudaGetSymbolAddress((void**)&COp, g_CO);

    const int flash_smem = (HD*SQ_STR + BN*SP_STR + BN*HD) * (int)sizeof(float); // 82432
    cudaFuncSetAttribute(flash_attn,
                         cudaFuncAttributeMaxDynamicSharedMemorySize, flash_smem);

    dim3 gg(MROWS / 128, DIMC / 128);   // 64 x 4
    dim3 bb(256);

    gemm_nt<false><<<gg, bb>>>(x, Wq,    Qp);
    gemm_nt<false><<<gg, bb>>>(x, Wk,    Kp);
    gemm_nt<false><<<gg, bb>>>(x, Wv,    Vp);
    gemm_nt<false><<<gg, bb>>>(x, Wconv, CIp);

    flash_attn<<<dim3(NSEQ / BM, NH, BATCH), 256, flash_smem>>>(Qp, Kp, Vp, Ap);

    gemm_nt<false><<<gg, bb>>>(Ap, Wattn, out);

    dwconv<<<(MROWS * DIMC) / 256, 256>>>(CIp, dwk, dwb, COp);

    gemm_nt<true><<<gg, bb>>>(COp, Wcout, out);
}

// round 3
// speedup vs baseline: 3.0013x; 3.0013x over previous
#include <cuda_runtime.h>
#include <math.h>

#define DIMC 512
#define NH 8
#define HD 64
#define NSEQ 4096
#define BATCH 2
#define MROWS (BATCH*NSEQ)   /* 8192 */

// -------- scratch (static device allocations; no cudaMalloc allowed) --------
__device__ float g_Q [MROWS*DIMC];
__device__ float g_K [MROWS*DIMC];
__device__ float g_V [MROWS*DIMC];
__device__ float g_A [MROWS*DIMC];
__device__ float g_CI[MROWS*DIMC];
__device__ float g_CO[MROWS*DIMC];

// ---------------------------------------------------------------------------
// tf32 helpers
// ---------------------------------------------------------------------------
__device__ __forceinline__ unsigned tf32r(float x) {
    unsigned u;
    asm("cvt.rna.tf32.f32 %0, %1;" : "=r"(u) : "f"(x));
    return u;
}
__device__ __forceinline__ float tf32f(float x) { return __uint_as_float(tf32r(x)); }

__device__ __forceinline__ void mma8(float* c,
                                     unsigned a0, unsigned a1, unsigned a2, unsigned a3,
                                     unsigned b0, unsigned b1)
{
    asm volatile(
        "mma.sync.aligned.m16n8k8.row.col.f32.tf32.tf32.f32 "
        "{%0,%1,%2,%3},{%4,%5,%6,%7},{%8,%9},{%0,%1,%2,%3};"
        : "+f"(c[0]), "+f"(c[1]), "+f"(c[2]), "+f"(c[3])
        : "r"(a0), "r"(a1), "r"(a2), "r"(a3), "r"(b0), "r"(b1));
}

// ---------------------------------------------------------------------------
// GEMM NT: C[M,512] = A[M,512] @ W[512,512]^T  (tf32 tensor cores)
// CTA tile 128x128, 8 warps (4m x 2n), warp tile 32x64, k-tile 32.
// smem stride 36 (== 4 mod 32) -> conflict-free fragment LDS.
// ---------------------------------------------------------------------------
template<bool ADD>
__global__ __launch_bounds__(256, 2)
void gemm_tf32(const float* __restrict__ A, const float* __restrict__ W,
               float* __restrict__ C)
{
    __shared__ float As[128][36];
    __shared__ float Ws[128][36];

    const int tid  = threadIdx.x;
    const int wid  = tid >> 5, lane = tid & 31;
    const int gid  = lane >> 2, tig = lane & 3;
    const int wm   = (wid & 3) * 32;
    const int wn   = (wid >> 2) * 64;
    const int m0   = blockIdx.x * 128;
    const int n0   = blockIdx.y * 128;

    float acc[2][8][4] = {};

    const int lr = tid >> 3;          // 0..31
    const int lc = (tid & 7) * 4;     // 0..28

    for (int k0 = 0; k0 < DIMC; k0 += 32) {
#pragma unroll
        for (int p = 0; p < 4; p++) {
            int row = lr + p * 32;
            float4 va = *(const float4*)&A[(size_t)(m0 + row) * DIMC + k0 + lc];
            As[row][lc+0] = tf32f(va.x); As[row][lc+1] = tf32f(va.y);
            As[row][lc+2] = tf32f(va.z); As[row][lc+3] = tf32f(va.w);
            float4 vw = *(const float4*)&W[(size_t)(n0 + row) * DIMC + k0 + lc];
            Ws[row][lc+0] = tf32f(vw.x); Ws[row][lc+1] = tf32f(vw.y);
            Ws[row][lc+2] = tf32f(vw.z); Ws[row][lc+3] = tf32f(vw.w);
        }
        __syncthreads();

#pragma unroll
        for (int kt = 0; kt < 4; kt++) {
            int kc = kt * 8 + tig;
            unsigned a[2][4];
#pragma unroll
            for (int mt = 0; mt < 2; mt++) {
                int r = wm + mt * 16 + gid;
                a[mt][0] = __float_as_uint(As[r    ][kc    ]);
                a[mt][1] = __float_as_uint(As[r + 8][kc    ]);
                a[mt][2] = __float_as_uint(As[r    ][kc + 4]);
                a[mt][3] = __float_as_uint(As[r + 8][kc + 4]);
            }
#pragma unroll
            for (int nt = 0; nt < 8; nt++) {
                int rn = wn + nt * 8 + gid;
                unsigned b0 = __float_as_uint(Ws[rn][kc    ]);
                unsigned b1 = __float_as_uint(Ws[rn][kc + 4]);
                mma8(acc[0][nt], a[0][0], a[0][1], a[0][2], a[0][3], b0, b1);
                mma8(acc[1][nt], a[1][0], a[1][1], a[1][2], a[1][3], b0, b1);
            }
        }
        __syncthreads();
    }

#pragma unroll
    for (int mt = 0; mt < 2; mt++) {
        int r0 = m0 + wm + mt * 16 + gid;
#pragma unroll
        for (int nt = 0; nt < 8; nt++) {
            int cix = n0 + wn + nt * 8 + 2 * tig;
            float2* p0 = (float2*)&C[(size_t)r0       * DIMC + cix];
            float2* p1 = (float2*)&C[(size_t)(r0 + 8) * DIMC + cix];
            if (ADD) {
                float2 o0 = *p0; o0.x += acc[mt][nt][0]; o0.y += acc[mt][nt][1]; *p0 = o0;
                float2 o1 = *p1; o1.x += acc[mt][nt][2]; o1.y += acc[mt][nt][3]; *p1 = o1;
            } else {
                *p0 = make_float2(acc[mt][nt][0], acc[mt][nt][1]);
                *p1 = make_float2(acc[mt][nt][2], acc[mt][nt][3]);
            }
        }
    }
}

// ---------------------------------------------------------------------------
// Flash attention, tf32 tensor cores. BM=128 (8 warps x 16 rows), BN=64, hd=64.
// Q fragments persist in registers; K/V tiles staged in smem each iter;
// P routed through a per-warp smem buffer (warp-private, __syncwarp only).
// smem strides: K 68 (4 mod 32), V 72 (8 mod 32), P 68 -> conflict-free LDS.
// ---------------------------------------------------------------------------
#define FK_STR 68
#define FV_STR 72
#define FP_STR 68
#define FLASH_SMEM_FLOATS (64*FK_STR + 64*FV_STR + 8*16*FP_STR)

__global__ __launch_bounds__(256, 1)
void flash_tf32(const float* __restrict__ Q, const float* __restrict__ K,
                const float* __restrict__ V, float* __restrict__ Aout)
{
    extern __shared__ float sm[];
    float* sK = sm;
    float* sV = sm + 64 * FK_STR;
    float* sP = sm + 64 * FK_STR + 64 * FV_STR;

    const int tid = threadIdx.x, wid = tid >> 5, lane = tid & 31;
    const int gid = lane >> 2, tig = lane & 3;
    const int m0 = blockIdx.x * 128;
    const int h  = blockIdx.y;
    const int b  = blockIdx.z;
    const float scale = 0.125f;

    const float* Qb = Q + (size_t)b * NSEQ * DIMC + h * HD;
    const float* Kb = K + (size_t)b * NSEQ * DIMC + h * HD;
    const float* Vb = V + (size_t)b * NSEQ * DIMC + h * HD;
    float* sPw = sP + wid * 16 * FP_STR;

    // ---- stage Q (pre-scaled, tf32-rounded) into sm[0..128*68), extract frags
    {
        int r = tid >> 4, c4 = (tid & 15) * 4;
#pragma unroll
        for (int p = 0; p < 8; p++) {
            int row = r + p * 16;
            float4 v = *(const float4*)&Qb[(size_t)(m0 + row) * DIMC + c4];
            float* d = sm + row * FK_STR + c4;
            d[0] = tf32f(v.x * scale); d[1] = tf32f(v.y * scale);
            d[2] = tf32f(v.z * scale); d[3] = tf32f(v.w * scale);
        }
    }
    __syncthreads();

    unsigned qf[8][4];
    {
        int r = wid * 16 + gid;
#pragma unroll
        for (int kt = 0; kt < 8; kt++) {
            int kc = kt * 8 + tig;
            qf[kt][0] = __float_as_uint(sm[(r    ) * FK_STR + kc    ]);
            qf[kt][1] = __float_as_uint(sm[(r + 8) * FK_STR + kc    ]);
            qf[kt][2] = __float_as_uint(sm[(r    ) * FK_STR + kc + 4]);
            qf[kt][3] = __float_as_uint(sm[(r + 8) * FK_STR + kc + 4]);
        }
    }

    float of[8][4] = {};
    float mrow[2] = { -1e30f, -1e30f };
    float lrow[2] = { 0.f, 0.f };

    for (int n0 = 0; n0 < NSEQ; n0 += 64) {
        __syncthreads();   // prev iter done with sK/sV (covers Q-frag extraction on iter 0)
        {
            int r = tid >> 4, c4 = (tid & 15) * 4;
#pragma unroll
            for (int p = 0; p < 4; p++) {
                int row = r + p * 16;
                float4 vk = *(const float4*)&Kb[(size_t)(n0 + row) * DIMC + c4];
                float* dk = sK + row * FK_STR + c4;
                dk[0] = tf32f(vk.x); dk[1] = tf32f(vk.y);
                dk[2] = tf32f(vk.z); dk[3] = tf32f(vk.w);
                float4 vv = *(const float4*)&Vb[(size_t)(n0 + row) * DIMC + c4];
                float* dv = sV + row * FV_STR + c4;
                dv[0] = tf32f(vv.x); dv[1] = tf32f(vv.y);
                dv[2] = tf32f(vv.z); dv[3] = tf32f(vv.w);
            }
        }
        __syncthreads();

        // ---- S = (Q*scale) @ K^T : C-frags s[8 ntiles][4]
        float s[8][4] = {};
#pragma unroll
        for (int kt = 0; kt < 8; kt++) {
            int kc = kt * 8 + tig;
#pragma unroll
            for (int nt = 0; nt < 8; nt++) {
                int rn = nt * 8 + gid;
                unsigned b0 = __float_as_uint(sK[rn * FK_STR + kc    ]);
                unsigned b1 = __float_as_uint(sK[rn * FK_STR + kc + 4]);
                mma8(s[nt], qf[kt][0], qf[kt][1], qf[kt][2], qf[kt][3], b0, b1);
            }
        }

        // ---- online softmax on fragments (row0 = gid -> c0/c1, row1 = gid+8 -> c2/c3)
#pragma unroll
        for (int hlf = 0; hlf < 2; hlf++) {
            float mx = -1e30f;
#pragma unroll
            for (int nt = 0; nt < 8; nt++)
                mx = fmaxf(mx, fmaxf(s[nt][hlf*2], s[nt][hlf*2+1]));
            mx = fmaxf(mx, __shfl_xor_sync(0xffffffffu, mx, 1));
            mx = fmaxf(mx, __shfl_xor_sync(0xffffffffu, mx, 2));
            float mn    = fmaxf(mrow[hlf], mx);
            float alpha = __expf(mrow[hlf] - mn);
            float sum   = 0.f;
#pragma unroll
            for (int nt = 0; nt < 8; nt++) {
                float e0 = __expf(s[nt][hlf*2  ] - mn);
                float e1 = __expf(s[nt][hlf*2+1] - mn);
                s[nt][hlf*2] = e0; s[nt][hlf*2+1] = e1;
                sum += e0 + e1;
            }
            sum += __shfl_xor_sync(0xffffffffu, sum, 1);
            sum += __shfl_xor_sync(0xffffffffu, sum, 2);
            lrow[hlf] = lrow[hlf] * alpha + sum;
            mrow[hlf] = mn;
#pragma unroll
            for (int nt = 0; nt < 8; nt++) {
                of[nt][hlf*2] *= alpha; of[nt][hlf*2+1] *= alpha;
            }
        }

        // ---- P to warp-private smem (C-frag layout -> A-frag reload)
#pragma unroll
        for (int nt = 0; nt < 8; nt++) {
            int cc = nt * 8 + 2 * tig;
            *(float2*)&sPw[(gid    ) * FP_STR + cc] = make_float2(tf32f(s[nt][0]), tf32f(s[nt][1]));
            *(float2*)&sPw[(gid + 8) * FP_STR + cc] = make_float2(tf32f(s[nt][2]), tf32f(s[nt][3]));
        }
        __syncwarp();

        // ---- O += P @ V
#pragma unroll
        for (int kt = 0; kt < 8; kt++) {
            int kc = kt * 8 + tig;
            unsigned pa0 = __float_as_uint(sPw[(gid    ) * FP_STR + kc    ]);
            unsigned pa1 = __float_as_uint(sPw[(gid + 8) * FP_STR + kc    ]);
            unsigned pa2 = __float_as_uint(sPw[(gid    ) * FP_STR + kc + 4]);
            unsigned pa3 = __float_as_uint(sPw[(gid + 8) * FP_STR + kc + 4]);
#pragma unroll
            for (int nt = 0; nt < 8; nt++) {
                unsigned b0 = __float_as_uint(sV[(kt*8 + tig    ) * FV_STR + nt*8 + gid]);
                unsigned b1 = __float_as_uint(sV[(kt*8 + tig + 4) * FV_STR + nt*8 + gid]);
                mma8(of[nt], pa0, pa1, pa2, pa3, b0, b1);
            }
        }
    }

    // ---- normalize + write
    float inv0 = 1.f / lrow[0], inv1 = 1.f / lrow[1];
    int r0 = m0 + wid * 16 + gid;
    float* Ob = Aout + (size_t)b * NSEQ * DIMC + h * HD;
#pragma unroll
    for (int nt = 0; nt < 8; nt++) {
        int cc = nt * 8 + 2 * tig;
        *(float2*)&Ob[(size_t)r0       * DIMC + cc] = make_float2(of[nt][0]*inv0, of[nt][1]*inv0);
        *(float2*)&Ob[(size_t)(r0 + 8) * DIMC + cc] = make_float2(of[nt][2]*inv1, of[nt][3]*inv1);
    }
}

// ---------------------------------------------------------------------------
// depthwise conv over N (k=3, pad=1) + bias  (exact fp32)
// ---------------------------------------------------------------------------
__global__ __launch_bounds__(256)
void dwconv(const float* __restrict__ CI, const float* __restrict__ kern,
            const float* __restrict__ bias, float* __restrict__ CO)
{
    int idx = blockIdx.x * blockDim.x + threadIdx.x;
    if (idx >= MROWS * DIMC) return;
    int c   = idx & (DIMC - 1);
    int row = idx >> 9;
    int n   = row & (NSEQ - 1);
    float k0 = kern[c*3+0], k1 = kern[c*3+1], k2 = kern[c*3+2];
    float acc = bias[c] + k1 * CI[idx];
    if (n > 0)        acc += k0 * CI[idx - DIMC];
    if (n < NSEQ - 1) acc += k2 * CI[idx + DIMC];
    CO[idx] = acc;
}

// ---------------------------------------------------------------------------
extern "C" void kernel_launch(void* const* d_in, const int* in_sizes, int n_in,
                              void* d_out, int out_size)
{
    const float* x     = (const float*)d_in[0];
    const float* Wq    = (const float*)d_in[1];
    const float* Wk    = (const float*)d_in[2];
    const float* Wv    = (const float*)d_in[3];
    const float* Wattn = (const float*)d_in[4];
    const float* Wconv = (const float*)d_in[5];
    const float* dwk   = (const float*)d_in[6];
    const float* dwb   = (const float*)d_in[7];
    const float* Wcout = (const float*)d_in[8];
    float* out = (float*)d_out;

    float *Qp, *Kp, *Vp, *Ap, *CIp, *COp;
    cudaGetSymbolAddress((void**)&Qp,  g_Q);
    cudaGetSymbolAddress((void**)&Kp,  g_K);
    cudaGetSymbolAddress((void**)&Vp,  g_V);
    cudaGetSymbolAddress((void**)&Ap,  g_A);
    cudaGetSymbolAddress((void**)&CIp, g_CI);
    cudaGetSymbolAddress((void**)&COp, g_CO);

    const int flash_smem = FLASH_SMEM_FLOATS * (int)sizeof(float);  // 70656
    cudaFuncSetAttribute(flash_tf32,
                         cudaFuncAttributeMaxDynamicSharedMemorySize, flash_smem);

    dim3 gg(MROWS / 128, DIMC / 128);   // 64 x 4
    dim3 bb(256);

    gemm_tf32<false><<<gg, bb>>>(x, Wq,    Qp);
    gemm_tf32<false><<<gg, bb>>>(x, Wk,    Kp);
    gemm_tf32<false><<<gg, bb>>>(x, Wv,    Vp);
    gemm_tf32<false><<<gg, bb>>>(x, Wconv, CIp);

    flash_tf32<<<dim3(NSEQ / 128, NH, BATCH), 256, flash_smem>>>(Qp, Kp, Vp, Ap);

    gemm_tf32<false><<<gg, bb>>>(Ap, Wattn, out);

    dwconv<<<(MROWS * DIMC) / 256, 256>>>(CIp, dwk, dwb, COp);

    gemm_tf32<true><<<gg, bb>>>(COp, Wcout, out);
}